// round 7
// baseline (speedup 1.0000x reference)
#include <cuda_runtime.h>
#include <cuda_fp16.h>
#include <cuda_fp8.h>
#include <cstdint>
#include <math_constants.h>

// Problem dims (fixed per reference)
#define DM   1024      // d_model
#define DF   4096      // d_ff
#define MROWS 16384    // 4 * 4096

#define INV2048 4.8828125e-4f

// ---------------------------------------------------------------------------
// Scratch (allocation-free: __device__ globals)
// ---------------------------------------------------------------------------
__device__ float   g_scores[(size_t)MROWS * DF];   // 256 MB fp32 logits
__device__ __half  g_phi[(size_t)MROWS * DF];      // probs (single fp16)
__device__ __half  g_xhi[(size_t)MROWS * DM];      // (xs*x) hi fp16
__device__ __half  g_whi[(size_t)DF * DM];         // (ws*w) hi fp16
__device__ uint8_t g_x8h[(size_t)MROWS * DM];      // e4m3(xs*x)
__device__ uint8_t g_x8l[(size_t)MROWS * DM];      // e4m3((xs*x - hi)*2048)
__device__ uint8_t g_w8h[(size_t)DF * DM];
__device__ uint8_t g_w8l[(size_t)DF * DM];
__device__ __half  g_wthi[(size_t)DM * DF];        // W^T [d][c] fp16
__device__ float   g_xscale[MROWS];
__device__ float   g_wscale[DF];

// ---------------------------------------------------------------------------
// PTX helpers
// ---------------------------------------------------------------------------
__device__ __forceinline__ uint32_t smem_u32_of(const void* p) {
    uint32_t a;
    asm("{ .reg .u64 t; cvta.to.shared.u64 t, %1; cvt.u32.u64 %0, t; }" : "=r"(a) : "l"(p));
    return a;
}

__device__ __forceinline__ void cp16(uint32_t s, const void* g) {
    asm volatile("cp.async.cg.shared.global [%0], [%1], 16;" :: "r"(s), "l"(g));
}

__device__ __forceinline__ void ldsm4(uint32_t* r, uint32_t a) {
    asm volatile("ldmatrix.sync.aligned.m8n8.x4.shared.b16 {%0,%1,%2,%3}, [%4];"
                 : "=r"(r[0]), "=r"(r[1]), "=r"(r[2]), "=r"(r[3]) : "r"(a));
}

__device__ __forceinline__ void mma16816(float* d, const uint32_t* a, const uint32_t* b) {
    asm volatile(
        "mma.sync.aligned.m16n8k16.row.col.f32.f16.f16.f32 "
        "{%0,%1,%2,%3}, {%4,%5,%6,%7}, {%8,%9}, {%0,%1,%2,%3};"
        : "+f"(d[0]), "+f"(d[1]), "+f"(d[2]), "+f"(d[3])
        : "r"(a[0]), "r"(a[1]), "r"(a[2]), "r"(a[3]), "r"(b[0]), "r"(b[1]));
}

__device__ __forceinline__ void mma8_16832(float* d, const uint32_t* a, const uint32_t* b) {
    asm volatile(
        "mma.sync.aligned.m16n8k32.row.col.f32.e4m3.e4m3.f32 "
        "{%0,%1,%2,%3}, {%4,%5,%6,%7}, {%8,%9}, {%0,%1,%2,%3};"
        : "+f"(d[0]), "+f"(d[1]), "+f"(d[2]), "+f"(d[3])
        : "r"(a[0]), "r"(a[1]), "r"(a[2]), "r"(a[3]), "r"(b[0]), "r"(b[1]));
}

// ---------------------------------------------------------------------------
// Kernel: per-row rms scale
// ---------------------------------------------------------------------------
__global__ void rms_scale_kernel(const float* __restrict__ X, float* __restrict__ out)
{
    const int row = blockIdx.x;
    const int tid = threadIdx.x;
    const float* p = X + (size_t)row * DM;

    float4 v = *(const float4*)(p + tid * 4);
    float s = v.x * v.x + v.y * v.y + v.z * v.z + v.w * v.w;

    __shared__ float red[256];
    red[tid] = s;
    __syncthreads();
    #pragma unroll
    for (int off = 128; off > 0; off >>= 1) {
        if (tid < off) red[tid] += red[tid + off];
        __syncthreads();
    }
    if (tid == 0)
        out[row] = rsqrtf(red[0] * (1.0f / DM) + 1e-6f);
}

// ---------------------------------------------------------------------------
// Kernel: fused scale + fp16 hi + fp8 (hi, scaled-lo) planes
// ---------------------------------------------------------------------------
__device__ __forceinline__ uint8_t f2e4m3(float v) {
    __nv_fp8_e4m3 f8(v);
    return *reinterpret_cast<uint8_t*>(&f8);
}

__global__ __launch_bounds__(256) void scale_split_kernel(
    const float* __restrict__ src, const float* __restrict__ scale,
    __half* __restrict__ hi, uint8_t* __restrict__ p8h, uint8_t* __restrict__ p8l)
{
    const size_t i = (size_t)blockIdx.x * 256 + threadIdx.x;  // one float4 per thread
    float4 v = ((const float4*)src)[i];
    const float s = scale[i >> 8];   // element row = (4i)>>10 = i>>8
    float sv[4] = {v.x * s, v.y * s, v.z * s, v.w * s};
    __half h[4];
    uchar4 c8h, c8l;
    uint8_t* h8 = &c8h.x;
    uint8_t* l8 = &c8l.x;
    #pragma unroll
    for (int j = 0; j < 4; j++) {
        h[j] = __float2half_rn(sv[j]);
        float lo = sv[j] - __half2float(h[j]);
        h8[j] = f2e4m3(sv[j]);
        l8[j] = f2e4m3(lo * 2048.0f);
    }
    __half2* H = (__half2*)(hi + 4 * i);
    H[0] = __halves2half2(h[0], h[1]);
    H[1] = __halves2half2(h[2], h[3]);
    ((uchar4*)p8h)[i] = c8h;
    ((uchar4*)p8l)[i] = c8l;
}

// ---------------------------------------------------------------------------
// Kernel: transpose  W[c,d] -> Wt[d,c]  (raw w, single fp16)
// ---------------------------------------------------------------------------
__global__ void wt_kernel(const float* __restrict__ w, __half* __restrict__ th)
{
    __shared__ float t[32][33];
    const int c = blockIdx.y * 32 + threadIdx.y;
    const int d = blockIdx.x * 32 + threadIdx.x;
    t[threadIdx.y][threadIdx.x] = w[(size_t)c * DM + d];
    __syncthreads();
    const int dd = blockIdx.x * 32 + threadIdx.y;
    const int cc = blockIdx.y * 32 + threadIdx.x;
    th[(size_t)dd * DF + cc] = __float2half_rn(t[threadIdx.x][threadIdx.y]);
}

// ---------------------------------------------------------------------------
// Kernel: row softmax over 4096, emits single fp16 probs
// ---------------------------------------------------------------------------
__global__ __launch_bounds__(256) void softmax_h(const float* __restrict__ S,
                                                 __half* __restrict__ PH)
{
    const int row = blockIdx.x;
    const int tid = threadIdx.x;
    const float* p = S + (size_t)row * DF + tid * 16;

    float v[16];
    #pragma unroll
    for (int j = 0; j < 4; j++) {
        float4 t = *(const float4*)(p + j * 4);
        v[j * 4 + 0] = t.x; v[j * 4 + 1] = t.y;
        v[j * 4 + 2] = t.z; v[j * 4 + 3] = t.w;
    }
    float lm = v[0];
    #pragma unroll
    for (int j = 1; j < 16; j++) lm = fmaxf(lm, v[j]);

    __shared__ float red[256];
    red[tid] = lm;
    __syncthreads();
    #pragma unroll
    for (int off = 128; off > 0; off >>= 1) {
        if (tid < off) red[tid] = fmaxf(red[tid], red[tid + off]);
        __syncthreads();
    }
    const float m = red[0];
    __syncthreads();

    float ls = 0.f;
    #pragma unroll
    for (int j = 0; j < 16; j++) {
        v[j] = __expf(v[j] - m);
        ls += v[j];
    }
    red[tid] = ls;
    __syncthreads();
    #pragma unroll
    for (int off = 128; off > 0; off >>= 1) {
        if (tid < off) red[tid] += red[tid + off];
        __syncthreads();
    }
    const float inv = 1.0f / red[0];

    __half2* ph2 = (__half2*)(PH + (size_t)row * DF + tid * 16);
    #pragma unroll
    for (int j = 0; j < 8; j++) {
        ph2[j] = __halves2half2(__float2half_rn(v[2 * j] * inv),
                                __float2half_rn(v[2 * j + 1] * inv));
    }
}

// ---------------------------------------------------------------------------
// GEMM1: mixed fp16/fp8 NT GEMM.
//   C = Ah*Bh (fp16, exact hi term) + [A8h*B8l + A8l*B8h] / 2048 (fp8 cross)
// BM=BN=128, BK=32, 8 warps (2x4), warp tile 64x32, 3-stage cp.async ring.
// Stage layout (45056 B):
//   Ah fp16 128x80B @0 | Bh fp16 @10240
//   A8h 128x48B @20480 | A8l @26624 | B8h @32768 | B8l @38912
// fp8 pitch 48B makes the 4B-chunk fragment loads bank-conflict-free.
// ---------------------------------------------------------------------------
#define STGM   45056
#define GSMEMM (3 * STGM)    // 135168

__global__ __launch_bounds__(256, 1) void gemm_mixed(
    const __half* __restrict__ Ah, const __half* __restrict__ Bh,
    const uint8_t* __restrict__ A8h, const uint8_t* __restrict__ A8l,
    const uint8_t* __restrict__ B8h, const uint8_t* __restrict__ B8l,
    float* __restrict__ C)
{
    extern __shared__ __align__(16) char smem[];
    const uint32_t sbase = smem_u32_of(smem);
    const int tid  = threadIdx.x;
    const int lane = tid & 31;
    const int wid  = tid >> 5;
    const int wm   = (wid >> 2) * 64;   // 0,64
    const int wn   = (wid & 3) * 32;    // 0..96
    const int bm   = blockIdx.y * 128;
    const int bn   = blockIdx.x * 128;
    const int KT   = DM / 32;           // 32

    // fp16 loader mapping
    const int lr = tid >> 2;
    const int lc = tid & 3;
    const __half* pAh = Ah + (size_t)(bm + lr) * DM + lc * 8;
    const __half* pBh = Bh + (size_t)(bn + lr) * DM + lc * 8;
    const uint32_t so16 = lr * 80 + lc * 16;
    // fp8 loader mapping
    const int r8 = tid >> 1;
    const int c8 = (tid & 1) * 16;
    const uint8_t* pA8h = A8h + (size_t)(bm + r8) * DM + c8;
    const uint8_t* pA8l = A8l + (size_t)(bm + r8) * DM + c8;
    const uint8_t* pB8h = B8h + (size_t)(bn + r8) * DM + c8;
    const uint8_t* pB8l = B8l + (size_t)(bn + r8) * DM + c8;
    const uint32_t so8 = r8 * 48 + c8;

    float accm[4][4][4];   // main (fp16 hi*hi)
    float accx[4][4][4];   // cross (fp8, scaled by 2048)
    #pragma unroll
    for (int i = 0; i < 4; i++)
        #pragma unroll
        for (int j = 0; j < 4; j++)
            #pragma unroll
            for (int k = 0; k < 4; k++) { accm[i][j][k] = 0.f; accx[i][j][k] = 0.f; }

#define LOAD_M(kt, slot)                                                      \
    do {                                                                      \
        const int _k0 = (kt) * 32;                                            \
        const uint32_t _sb = sbase + (slot) * STGM;                           \
        cp16(_sb + so16,          pAh + _k0);                                 \
        cp16(_sb + so16 + 5120,   pAh + _k0 + (size_t)64 * DM);               \
        cp16(_sb + 10240 + so16,        pBh + _k0);                           \
        cp16(_sb + 10240 + so16 + 5120, pBh + _k0 + (size_t)64 * DM);         \
        cp16(_sb + 20480 + so8, pA8h + _k0);                                  \
        cp16(_sb + 26624 + so8, pA8l + _k0);                                  \
        cp16(_sb + 32768 + so8, pB8h + _k0);                                  \
        cp16(_sb + 38912 + so8, pB8l + _k0);                                  \
    } while (0)

    LOAD_M(0, 0); asm volatile("cp.async.commit_group;" ::: "memory");
    LOAD_M(1, 1); asm volatile("cp.async.commit_group;" ::: "memory");

    // fp16 ldmatrix offsets
    const uint32_t aoff = ((wm + (lane & 15)) * 40 + ((lane >> 4) << 3)) * 2;
    const uint32_t boff = ((wn + (lane & 7) + ((lane >> 4) << 3)) * 40 + (lane & 8)) * 2;
    // fp8 fragment offsets (bytes within plane)
    const uint32_t a8off = (wm + (lane >> 2)) * 48 + (lane & 3) * 4;
    const uint32_t b8off = (wn + (lane >> 2)) * 48 + (lane & 3) * 4;

    int slot = 0, nslot = 2;
    for (int kt = 0; kt < KT; ++kt) {
        asm volatile("cp.async.wait_group 1;" ::: "memory");
        __syncthreads();
        const uint32_t sb = sbase + slot * STGM;
        const char* sp = smem + slot * STGM;

        // --- fp16 main term (two k16 halves) ---
        #pragma unroll
        for (int ks = 0; ks < 2; ++ks) {
            const uint32_t kc2 = ks * 32;
            uint32_t af[4][4], bf[4][2];
            #pragma unroll
            for (int mt = 0; mt < 4; mt++)
                ldsm4(af[mt], sb + aoff + kc2 + mt * 1280);
            #pragma unroll
            for (int g = 0; g < 2; g++) {
                uint32_t r[4];
                ldsm4(r, sb + 10240 + boff + kc2 + g * 1280);
                bf[g * 2][0] = r[0]; bf[g * 2][1] = r[1];
                bf[g * 2 + 1][0] = r[2]; bf[g * 2 + 1][1] = r[3];
            }
            #pragma unroll
            for (int mt = 0; mt < 4; mt++)
                #pragma unroll
                for (int nt = 0; nt < 4; nt++)
                    mma16816(accm[mt][nt], af[mt], bf[nt]);
        }

        // --- fp8 cross terms (one k32 step) ---
        {
            const char* pa_h = sp + 20480 + a8off;
            const char* pa_l = sp + 26624 + a8off;
            const char* pb_h = sp + 32768 + b8off;
            const char* pb_l = sp + 38912 + b8off;
            uint32_t a8h[4][4], a8l[4][4], b8h[4][2], b8l[4][2];
            #pragma unroll
            for (int mt = 0; mt < 4; mt++) {
                const int o = mt * 768;   // 16 rows * 48B
                a8h[mt][0] = *(const uint32_t*)(pa_h + o);
                a8h[mt][1] = *(const uint32_t*)(pa_h + o + 384);
                a8h[mt][2] = *(const uint32_t*)(pa_h + o + 16);
                a8h[mt][3] = *(const uint32_t*)(pa_h + o + 400);
                a8l[mt][0] = *(const uint32_t*)(pa_l + o);
                a8l[mt][1] = *(const uint32_t*)(pa_l + o + 384);
                a8l[mt][2] = *(const uint32_t*)(pa_l + o + 16);
                a8l[mt][3] = *(const uint32_t*)(pa_l + o + 400);
            }
            #pragma unroll
            for (int nt = 0; nt < 4; nt++) {
                const int o = nt * 384;   // 8 rows * 48B
                b8h[nt][0] = *(const uint32_t*)(pb_h + o);
                b8h[nt][1] = *(const uint32_t*)(pb_h + o + 16);
                b8l[nt][0] = *(const uint32_t*)(pb_l + o);
                b8l[nt][1] = *(const uint32_t*)(pb_l + o + 16);
            }
            #pragma unroll
            for (int mt = 0; mt < 4; mt++)
                #pragma unroll
                for (int nt = 0; nt < 4; nt++) {
                    mma8_16832(accx[mt][nt], a8h[mt], b8l[nt]);  // hi * lo
                    mma8_16832(accx[mt][nt], a8l[mt], b8h[nt]);  // lo * hi
                }
        }

        __syncthreads();
        if (kt + 2 < KT) LOAD_M(kt + 2, nslot);
        asm volatile("cp.async.commit_group;" ::: "memory");
        slot = (slot == 2) ? 0 : slot + 1;
        nslot = (nslot == 2) ? 0 : nslot + 1;
    }

    #pragma unroll
    for (int mt = 0; mt < 4; mt++) {
        const int row = bm + wm + mt * 16 + (lane >> 2);
        float* r0 = C + (size_t)row * DF + bn + wn + (lane & 3) * 2;
        float* r1 = r0 + (size_t)8 * DF;
        #pragma unroll
        for (int nt = 0; nt < 4; nt++) {
            *(float2*)(r0 + nt * 8) = make_float2(
                accm[mt][nt][0] + accx[mt][nt][0] * INV2048,
                accm[mt][nt][1] + accx[mt][nt][1] * INV2048);
            *(float2*)(r1 + nt * 8) = make_float2(
                accm[mt][nt][2] + accx[mt][nt][2] * INV2048,
                accm[mt][nt][3] + accx[mt][nt][3] * INV2048);
        }
    }
#undef LOAD_M
}

// ---------------------------------------------------------------------------
// GEMM2: single-fp16 NT GEMM (1 term) — out = P @ W.
// BM=BN=128, BK=32, warp tile 64x32, 4-stage (R5-proven).
// ---------------------------------------------------------------------------
#define STAGEB1 20480
#define GSMEM1  (4 * STAGEB1)   // 81920

__global__ __launch_bounds__(256, 1) void gemm_h16(
    const __half* __restrict__ A, const __half* __restrict__ B,
    float* __restrict__ C, int lda, int ldb, int ldc, int KT)
{
    extern __shared__ __align__(16) char smem[];
    const uint32_t sbase = smem_u32_of(smem);
    const int tid  = threadIdx.x;
    const int lane = tid & 31;
    const int wid  = tid >> 5;
    const int wm   = (wid >> 2) * 64;
    const int wn   = (wid & 3) * 32;
    const int bm   = blockIdx.y * 128;
    const int bn   = blockIdx.x * 128;

    const int lr = tid >> 2;
    const int lc = tid & 3;
    const __half* pA = A + (size_t)(bm + lr) * lda + lc * 8;
    const __half* pB = B + (size_t)(bn + lr) * ldb + lc * 8;
    const size_t rstepA = (size_t)64 * lda;
    const size_t rstepB = (size_t)64 * ldb;
    const uint32_t so = lr * 80 + lc * 16;

    float acc[4][4][4];
    #pragma unroll
    for (int i = 0; i < 4; i++)
        #pragma unroll
        for (int j = 0; j < 4; j++)
            #pragma unroll
            for (int k = 0; k < 4; k++) acc[i][j][k] = 0.f;

#define LOAD_S1(kt)                                                           \
    do {                                                                      \
        const int _k0 = (kt) * 32;                                            \
        const uint32_t _sb = sbase + ((kt) & 3) * STAGEB1 + so;               \
        cp16(_sb + 0,     pA + _k0);                                          \
        cp16(_sb + 5120,  pA + _k0 + rstepA);                                 \
        cp16(_sb + 10240, pB + _k0);                                          \
        cp16(_sb + 15360, pB + _k0 + rstepB);                                 \
    } while (0)

    LOAD_S1(0); asm volatile("cp.async.commit_group;" ::: "memory");
    LOAD_S1(1); asm volatile("cp.async.commit_group;" ::: "memory");
    LOAD_S1(2); asm volatile("cp.async.commit_group;" ::: "memory");

    const uint32_t aoff = ((wm + (lane & 15)) * 40 + ((lane >> 4) << 3)) * 2;
    const uint32_t boff = ((wn + (lane & 7) + ((lane >> 4) << 3)) * 40 + (lane & 8)) * 2;

    for (int kt = 0; kt < KT; ++kt) {
        asm volatile("cp.async.wait_group 2;" ::: "memory");
        __syncthreads();
        const uint32_t sb = sbase + (kt & 3) * STAGEB1;

        #pragma unroll
        for (int ks = 0; ks < 2; ++ks) {
            const uint32_t kc2 = ks * 32;
            uint32_t af[4][4], bf[4][2];
            #pragma unroll
            for (int mt = 0; mt < 4; mt++)
                ldsm4(af[mt], sb + aoff + kc2 + mt * 1280);
            #pragma unroll
            for (int n2 = 0; n2 < 2; n2++) {
                uint32_t r[4];
                ldsm4(r, sb + 10240 + boff + kc2 + n2 * 1280);
                bf[n2 * 2][0] = r[0]; bf[n2 * 2][1] = r[1];
                bf[n2 * 2 + 1][0] = r[2]; bf[n2 * 2 + 1][1] = r[3];
            }
            #pragma unroll
            for (int mt = 0; mt < 4; mt++)
                #pragma unroll
                for (int nt = 0; nt < 4; nt++)
                    mma16816(acc[mt][nt], af[mt], bf[nt]);
        }
        __syncthreads();
        if (kt + 3 < KT) LOAD_S1(kt + 3);
        asm volatile("cp.async.commit_group;" ::: "memory");
    }

    #pragma unroll
    for (int mt = 0; mt < 4; mt++) {
        const int row = bm + wm + mt * 16 + (lane >> 2);
        float* r0 = C + (size_t)row * ldc + bn + wn + (lane & 3) * 2;
        float* r1 = r0 + (size_t)8 * ldc;
        #pragma unroll
        for (int nt = 0; nt < 4; nt++) {
            *(float2*)(r0 + nt * 8) = make_float2(acc[mt][nt][0], acc[mt][nt][1]);
            *(float2*)(r1 + nt * 8) = make_float2(acc[mt][nt][2], acc[mt][nt][3]);
        }
    }
#undef LOAD_S1
}

// ---------------------------------------------------------------------------
// Launch
// ---------------------------------------------------------------------------
extern "C" void kernel_launch(void* const* d_in, const int* in_sizes, int n_in,
                              void* d_out, int out_size)
{
    const float* x = (const float*)d_in[0];   // [16384, 1024]
    const float* w = (const float*)d_in[1];   // [4096, 1024]
    float* out = (float*)d_out;               // [16384, 1024]

    float *xscale, *wscale, *scores;
    __half *xhi, *whi, *wthi, *phi;
    uint8_t *x8h, *x8l, *w8h, *w8l;
    cudaGetSymbolAddress((void**)&xscale, g_xscale);
    cudaGetSymbolAddress((void**)&wscale, g_wscale);
    cudaGetSymbolAddress((void**)&scores, g_scores);
    cudaGetSymbolAddress((void**)&xhi, g_xhi);
    cudaGetSymbolAddress((void**)&whi, g_whi);
    cudaGetSymbolAddress((void**)&wthi, g_wthi);
    cudaGetSymbolAddress((void**)&phi, g_phi);
    cudaGetSymbolAddress((void**)&x8h, g_x8h);
    cudaGetSymbolAddress((void**)&x8l, g_x8l);
    cudaGetSymbolAddress((void**)&w8h, g_w8h);
    cudaGetSymbolAddress((void**)&w8l, g_w8l);

    cudaFuncSetAttribute(gemm_mixed, cudaFuncAttributeMaxDynamicSharedMemorySize,
                         GSMEMM);
    cudaFuncSetAttribute(gemm_h16, cudaFuncAttributeMaxDynamicSharedMemorySize,
                         GSMEM1);

    // Prep
    rms_scale_kernel<<<MROWS, 256>>>(x, xscale);
    rms_scale_kernel<<<DF,    256>>>(w, wscale);
    scale_split_kernel<<<(MROWS * (DM / 4)) / 256, 256>>>(x, xscale, xhi, x8h, x8l);
    scale_split_kernel<<<(DF * (DM / 4)) / 256, 256>>>(w, wscale, whi, w8h, w8l);
    {
        dim3 g(DM / 32, DF / 32), b(32, 32);
        wt_kernel<<<g, b>>>(w, wthi);
    }

    // GEMM1 (fp16 hi*hi + fp8 cross): scores
    {
        dim3 g(DF / 128, MROWS / 128);   // 32 x 128
        gemm_mixed<<<g, 256, GSMEMM>>>(xhi, whi, x8h, x8l, w8h, w8l, scores);
    }

    // softmax rows -> fp16 probs
    softmax_h<<<MROWS, 256>>>(scores, phi);

    // GEMM2 (1-term fp16)
    {
        dim3 g(DM / 128, MROWS / 128);   // 8 x 128
        gemm_h16<<<g, 256, GSMEM1>>>(phi, wthi, out, DF, DF, DM, DF / 32);
    }
}

// round 8
// speedup vs baseline: 1.0504x; 1.0504x over previous
#include <cuda_runtime.h>
#include <cuda_fp16.h>
#include <cuda_fp8.h>
#include <cstdint>
#include <math_constants.h>

// Problem dims (fixed per reference)
#define DM   1024      // d_model
#define DF   4096      // d_ff
#define MROWS 16384    // 4 * 4096

#define INV2048 4.8828125e-4f

// ---------------------------------------------------------------------------
// Scratch (allocation-free: __device__ globals)
// ---------------------------------------------------------------------------
__device__ float   g_scores[(size_t)MROWS * DF];   // 256 MB fp32 logits
__device__ __half  g_phi[(size_t)MROWS * DF];      // probs (single fp16)
__device__ __half  g_xhi[(size_t)MROWS * DM];      // (xs*x) hi fp16
__device__ __half  g_whi[(size_t)DF * DM];         // (ws*w) hi fp16
__device__ uint8_t g_x8h[(size_t)MROWS * DM];      // e4m3(xs*x)
__device__ uint8_t g_x8l[(size_t)MROWS * DM];      // e4m3((xs*x - hi)*2048)
__device__ uint8_t g_w8h[(size_t)DF * DM];
__device__ uint8_t g_w8l[(size_t)DF * DM];
__device__ __half  g_wthi[(size_t)DM * DF];        // W^T [d][c] fp16
__device__ float   g_xscale[MROWS];                // (unused placeholder)
__device__ float   g_wscale[DF];                   // (unused placeholder)

// ---------------------------------------------------------------------------
// PTX helpers
// ---------------------------------------------------------------------------
__device__ __forceinline__ uint32_t smem_u32_of(const void* p) {
    uint32_t a;
    asm("{ .reg .u64 t; cvta.to.shared.u64 t, %1; cvt.u32.u64 %0, t; }" : "=r"(a) : "l"(p));
    return a;
}

__device__ __forceinline__ void cp16(uint32_t s, const void* g) {
    asm volatile("cp.async.cg.shared.global [%0], [%1], 16;" :: "r"(s), "l"(g));
}

__device__ __forceinline__ void ldsm4(uint32_t* r, uint32_t a) {
    asm volatile("ldmatrix.sync.aligned.m8n8.x4.shared.b16 {%0,%1,%2,%3}, [%4];"
                 : "=r"(r[0]), "=r"(r[1]), "=r"(r[2]), "=r"(r[3]) : "r"(a));
}

__device__ __forceinline__ void mma16816(float* d, const uint32_t* a, const uint32_t* b) {
    asm volatile(
        "mma.sync.aligned.m16n8k16.row.col.f32.f16.f16.f32 "
        "{%0,%1,%2,%3}, {%4,%5,%6,%7}, {%8,%9}, {%0,%1,%2,%3};"
        : "+f"(d[0]), "+f"(d[1]), "+f"(d[2]), "+f"(d[3])
        : "r"(a[0]), "r"(a[1]), "r"(a[2]), "r"(a[3]), "r"(b[0]), "r"(b[1]));
}

// fp8 e4m3 mma with fp16 accumulator (2-reg D fragment)
__device__ __forceinline__ void mma8h(uint32_t* d, const uint32_t* a, const uint32_t* b) {
    asm volatile(
        "mma.sync.aligned.m16n8k32.row.col.f16.e4m3.e4m3.f16 "
        "{%0,%1}, {%2,%3,%4,%5}, {%6,%7}, {%0,%1};"
        : "+r"(d[0]), "+r"(d[1])
        : "r"(a[0]), "r"(a[1]), "r"(a[2]), "r"(a[3]), "r"(b[0]), "r"(b[1]));
}

// ---------------------------------------------------------------------------
// Kernel: fused per-row rmsnorm + fp16 hi + fp8 (hi, scaled-lo) planes.
// One block (256 thr) per row of 1024 floats; thread t owns elements 4t..4t+3.
// ---------------------------------------------------------------------------
__device__ __forceinline__ uint8_t f2e4m3(float v) {
    __nv_fp8_e4m3 f8(v);
    return *reinterpret_cast<uint8_t*>(&f8);
}

__global__ __launch_bounds__(256) void rms_split_kernel(
    const float* __restrict__ src,
    __half* __restrict__ hi, uint8_t* __restrict__ p8h, uint8_t* __restrict__ p8l)
{
    const int row = blockIdx.x;
    const int tid = threadIdx.x;
    const size_t base = (size_t)row * DM;

    float4 v = *(const float4*)(src + base + tid * 4);
    float ss = v.x * v.x + v.y * v.y + v.z * v.z + v.w * v.w;

    __shared__ float red[256];
    red[tid] = ss;
    __syncthreads();
    #pragma unroll
    for (int off = 128; off > 0; off >>= 1) {
        if (tid < off) red[tid] += red[tid + off];
        __syncthreads();
    }
    const float s = rsqrtf(red[0] * (1.0f / DM) + 1e-6f);

    float sv[4] = {v.x * s, v.y * s, v.z * s, v.w * s};
    __half h[4];
    uchar4 c8h, c8l;
    uint8_t* h8 = &c8h.x;
    uint8_t* l8 = &c8l.x;
    #pragma unroll
    for (int j = 0; j < 4; j++) {
        h[j] = __float2half_rn(sv[j]);
        float lo = sv[j] - __half2float(h[j]);
        h8[j] = f2e4m3(sv[j]);
        l8[j] = f2e4m3(lo * 2048.0f);
    }
    __half2* H = (__half2*)(hi + base + tid * 4);
    H[0] = __halves2half2(h[0], h[1]);
    H[1] = __halves2half2(h[2], h[3]);
    *(uchar4*)(p8h + base + tid * 4) = c8h;
    *(uchar4*)(p8l + base + tid * 4) = c8l;
}

// ---------------------------------------------------------------------------
// Kernel: transpose  W[c,d] -> Wt[d,c]  (raw w, single fp16)
// ---------------------------------------------------------------------------
__global__ void wt_kernel(const float* __restrict__ w, __half* __restrict__ th)
{
    __shared__ float t[32][33];
    const int c = blockIdx.y * 32 + threadIdx.y;
    const int d = blockIdx.x * 32 + threadIdx.x;
    t[threadIdx.y][threadIdx.x] = w[(size_t)c * DM + d];
    __syncthreads();
    const int dd = blockIdx.x * 32 + threadIdx.y;
    const int cc = blockIdx.y * 32 + threadIdx.x;
    th[(size_t)dd * DF + cc] = __float2half_rn(t[threadIdx.x][threadIdx.y]);
}

// ---------------------------------------------------------------------------
// Kernel: row softmax over 4096, emits single fp16 probs
// ---------------------------------------------------------------------------
__global__ __launch_bounds__(256) void softmax_h(const float* __restrict__ S,
                                                 __half* __restrict__ PH)
{
    const int row = blockIdx.x;
    const int tid = threadIdx.x;
    const float* p = S + (size_t)row * DF + tid * 16;

    float v[16];
    #pragma unroll
    for (int j = 0; j < 4; j++) {
        float4 t = *(const float4*)(p + j * 4);
        v[j * 4 + 0] = t.x; v[j * 4 + 1] = t.y;
        v[j * 4 + 2] = t.z; v[j * 4 + 3] = t.w;
    }
    float lm = v[0];
    #pragma unroll
    for (int j = 1; j < 16; j++) lm = fmaxf(lm, v[j]);

    __shared__ float red[256];
    red[tid] = lm;
    __syncthreads();
    #pragma unroll
    for (int off = 128; off > 0; off >>= 1) {
        if (tid < off) red[tid] = fmaxf(red[tid], red[tid + off]);
        __syncthreads();
    }
    const float m = red[0];
    __syncthreads();

    float ls = 0.f;
    #pragma unroll
    for (int j = 0; j < 16; j++) {
        v[j] = __expf(v[j] - m);
        ls += v[j];
    }
    red[tid] = ls;
    __syncthreads();
    #pragma unroll
    for (int off = 128; off > 0; off >>= 1) {
        if (tid < off) red[tid] += red[tid + off];
        __syncthreads();
    }
    const float inv = 1.0f / red[0];

    __half2* ph2 = (__half2*)(PH + (size_t)row * DF + tid * 16);
    #pragma unroll
    for (int j = 0; j < 8; j++) {
        ph2[j] = __halves2half2(__float2half_rn(v[2 * j] * inv),
                                __float2half_rn(v[2 * j + 1] * inv));
    }
}

// ---------------------------------------------------------------------------
// GEMM1: mixed fp16/fp8 NT GEMM.
//   C = Ah*Bh (fp16, f32 acc) + [A8h*B8l + A8l*B8h] / 2048 (fp8, f16 acc)
// BM=BN=128, BK=32, 8 warps (2x4), warp tile 64x32, 3-stage cp.async ring.
// Stage (45056 B): Ah fp16 128x80B @0 | Bh @10240
//                  A8h 128x48B @20480 | A8l @26624 | B8h @32768 | B8l @38912
// Register budget: accm 128 f32 + accx 32 u32 (f16x2) -> no spills.
// ---------------------------------------------------------------------------
#define STGM   45056
#define GSMEMM (3 * STGM)    // 135168

__global__ __launch_bounds__(256, 1) void gemm_mixed(
    const __half* __restrict__ Ah, const __half* __restrict__ Bh,
    const uint8_t* __restrict__ A8h, const uint8_t* __restrict__ A8l,
    const uint8_t* __restrict__ B8h, const uint8_t* __restrict__ B8l,
    float* __restrict__ C)
{
    extern __shared__ __align__(16) char smem[];
    const uint32_t sbase = smem_u32_of(smem);
    const int tid  = threadIdx.x;
    const int lane = tid & 31;
    const int wid  = tid >> 5;
    const int wm   = (wid >> 2) * 64;   // 0,64
    const int wn   = (wid & 3) * 32;    // 0..96
    const int bm   = blockIdx.y * 128;
    const int bn   = blockIdx.x * 128;
    const int KT   = DM / 32;           // 32

    // fp16 loader mapping
    const int lr = tid >> 2;
    const int lc = tid & 3;
    const __half* pAh = Ah + (size_t)(bm + lr) * DM + lc * 8;
    const __half* pBh = Bh + (size_t)(bn + lr) * DM + lc * 8;
    const uint32_t so16 = lr * 80 + lc * 16;
    // fp8 loader mapping
    const int r8 = tid >> 1;
    const int c8 = (tid & 1) * 16;
    const uint8_t* pA8h = A8h + (size_t)(bm + r8) * DM + c8;
    const uint8_t* pA8l = A8l + (size_t)(bm + r8) * DM + c8;
    const uint8_t* pB8h = B8h + (size_t)(bn + r8) * DM + c8;
    const uint8_t* pB8l = B8l + (size_t)(bn + r8) * DM + c8;
    const uint32_t so8 = r8 * 48 + c8;

    float    accm[4][4][4];   // fp16 main, f32 acc
    uint32_t accx[4][4][2];   // fp8 cross, f16 acc (packed half2 pairs)
    #pragma unroll
    for (int i = 0; i < 4; i++)
        #pragma unroll
        for (int j = 0; j < 4; j++) {
            #pragma unroll
            for (int k = 0; k < 4; k++) accm[i][j][k] = 0.f;
            accx[i][j][0] = 0u; accx[i][j][1] = 0u;
        }

#define LOAD_M(kt, slot)                                                      \
    do {                                                                      \
        const int _k0 = (kt) * 32;                                            \
        const uint32_t _sb = sbase + (slot) * STGM;                           \
        cp16(_sb + so16,          pAh + _k0);                                 \
        cp16(_sb + so16 + 5120,   pAh + _k0 + (size_t)64 * DM);               \
        cp16(_sb + 10240 + so16,        pBh + _k0);                           \
        cp16(_sb + 10240 + so16 + 5120, pBh + _k0 + (size_t)64 * DM);         \
        cp16(_sb + 20480 + so8, pA8h + _k0);                                  \
        cp16(_sb + 26624 + so8, pA8l + _k0);                                  \
        cp16(_sb + 32768 + so8, pB8h + _k0);                                  \
        cp16(_sb + 38912 + so8, pB8l + _k0);                                  \
    } while (0)

    LOAD_M(0, 0); asm volatile("cp.async.commit_group;" ::: "memory");
    LOAD_M(1, 1); asm volatile("cp.async.commit_group;" ::: "memory");

    const uint32_t aoff = ((wm + (lane & 15)) * 40 + ((lane >> 4) << 3)) * 2;
    const uint32_t boff = ((wn + (lane & 7) + ((lane >> 4) << 3)) * 40 + (lane & 8)) * 2;
    const uint32_t a8off = (wm + (lane >> 2)) * 48 + (lane & 3) * 4;
    const uint32_t b8off = (wn + (lane >> 2)) * 48 + (lane & 3) * 4;

    int slot = 0, nslot = 2;
    for (int kt = 0; kt < KT; ++kt) {
        asm volatile("cp.async.wait_group 1;" ::: "memory");
        __syncthreads();
        const uint32_t sb = sbase + slot * STGM;
        const char* sp = smem + slot * STGM;

        // --- fp16 main term (two k16 halves) ---
        #pragma unroll
        for (int ks = 0; ks < 2; ++ks) {
            const uint32_t kc2 = ks * 32;
            uint32_t af[4][4], bf[4][2];
            #pragma unroll
            for (int mt = 0; mt < 4; mt++)
                ldsm4(af[mt], sb + aoff + kc2 + mt * 1280);
            #pragma unroll
            for (int g = 0; g < 2; g++) {
                uint32_t r[4];
                ldsm4(r, sb + 10240 + boff + kc2 + g * 1280);
                bf[g * 2][0] = r[0]; bf[g * 2][1] = r[1];
                bf[g * 2 + 1][0] = r[2]; bf[g * 2 + 1][1] = r[3];
            }
            #pragma unroll
            for (int mt = 0; mt < 4; mt++)
                #pragma unroll
                for (int nt = 0; nt < 4; nt++)
                    mma16816(accm[mt][nt], af[mt], bf[nt]);
        }

        // --- fp8 cross terms (one k32 step, f16 acc) ---
        {
            const char* pa_h = sp + 20480 + a8off;
            const char* pa_l = sp + 26624 + a8off;
            const char* pb_h = sp + 32768 + b8off;
            const char* pb_l = sp + 38912 + b8off;
            uint32_t a8h[4][4], a8l[4][4], b8h[4][2], b8l[4][2];
            #pragma unroll
            for (int mt = 0; mt < 4; mt++) {
                const int o = mt * 768;   // 16 rows * 48B
                a8h[mt][0] = *(const uint32_t*)(pa_h + o);
                a8h[mt][1] = *(const uint32_t*)(pa_h + o + 384);
                a8h[mt][2] = *(const uint32_t*)(pa_h + o + 16);
                a8h[mt][3] = *(const uint32_t*)(pa_h + o + 400);
                a8l[mt][0] = *(const uint32_t*)(pa_l + o);
                a8l[mt][1] = *(const uint32_t*)(pa_l + o + 384);
                a8l[mt][2] = *(const uint32_t*)(pa_l + o + 16);
                a8l[mt][3] = *(const uint32_t*)(pa_l + o + 400);
            }
            #pragma unroll
            for (int nt = 0; nt < 4; nt++) {
                const int o = nt * 384;   // 8 rows * 48B
                b8h[nt][0] = *(const uint32_t*)(pb_h + o);
                b8h[nt][1] = *(const uint32_t*)(pb_h + o + 16);
                b8l[nt][0] = *(const uint32_t*)(pb_l + o);
                b8l[nt][1] = *(const uint32_t*)(pb_l + o + 16);
            }
            #pragma unroll
            for (int mt = 0; mt < 4; mt++)
                #pragma unroll
                for (int nt = 0; nt < 4; nt++) {
                    mma8h(accx[mt][nt], a8h[mt], b8l[nt]);  // hi * lo
                    mma8h(accx[mt][nt], a8l[mt], b8h[nt]);  // lo * hi
                }
        }

        __syncthreads();
        if (kt + 2 < KT) LOAD_M(kt + 2, nslot);
        asm volatile("cp.async.commit_group;" ::: "memory");
        slot = (slot == 2) ? 0 : slot + 1;
        nslot = (nslot == 2) ? 0 : nslot + 1;
    }

    #pragma unroll
    for (int mt = 0; mt < 4; mt++) {
        const int row = bm + wm + mt * 16 + (lane >> 2);
        float* r0 = C + (size_t)row * DF + bn + wn + (lane & 3) * 2;
        float* r1 = r0 + (size_t)8 * DF;
        #pragma unroll
        for (int nt = 0; nt < 4; nt++) {
            const __half2 x01 = *reinterpret_cast<const __half2*>(&accx[mt][nt][0]);
            const __half2 x23 = *reinterpret_cast<const __half2*>(&accx[mt][nt][1]);
            *(float2*)(r0 + nt * 8) = make_float2(
                accm[mt][nt][0] + __low2float(x01)  * INV2048,
                accm[mt][nt][1] + __high2float(x01) * INV2048);
            *(float2*)(r1 + nt * 8) = make_float2(
                accm[mt][nt][2] + __low2float(x23)  * INV2048,
                accm[mt][nt][3] + __high2float(x23) * INV2048);
        }
    }
#undef LOAD_M
}

// ---------------------------------------------------------------------------
// GEMM2: single-fp16 NT GEMM (1 term) — out = P @ W.
// BM=BN=128, BK=32, warp tile 64x32, 4-stage (R5-proven).
// ---------------------------------------------------------------------------
#define STAGEB1 20480
#define GSMEM1  (4 * STAGEB1)   // 81920

__global__ __launch_bounds__(256, 1) void gemm_h16(
    const __half* __restrict__ A, const __half* __restrict__ B,
    float* __restrict__ C, int lda, int ldb, int ldc, int KT)
{
    extern __shared__ __align__(16) char smem[];
    const uint32_t sbase = smem_u32_of(smem);
    const int tid  = threadIdx.x;
    const int lane = tid & 31;
    const int wid  = tid >> 5;
    const int wm   = (wid >> 2) * 64;
    const int wn   = (wid & 3) * 32;
    const int bm   = blockIdx.y * 128;
    const int bn   = blockIdx.x * 128;

    const int lr = tid >> 2;
    const int lc = tid & 3;
    const __half* pA = A + (size_t)(bm + lr) * lda + lc * 8;
    const __half* pB = B + (size_t)(bn + lr) * ldb + lc * 8;
    const size_t rstepA = (size_t)64 * lda;
    const size_t rstepB = (size_t)64 * ldb;
    const uint32_t so = lr * 80 + lc * 16;

    float acc[4][4][4];
    #pragma unroll
    for (int i = 0; i < 4; i++)
        #pragma unroll
        for (int j = 0; j < 4; j++)
            #pragma unroll
            for (int k = 0; k < 4; k++) acc[i][j][k] = 0.f;

#define LOAD_S1(kt)                                                           \
    do {                                                                      \
        const int _k0 = (kt) * 32;                                            \
        const uint32_t _sb = sbase + ((kt) & 3) * STAGEB1 + so;               \
        cp16(_sb + 0,     pA + _k0);                                          \
        cp16(_sb + 5120,  pA + _k0 + rstepA);                                 \
        cp16(_sb + 10240, pB + _k0);                                          \
        cp16(_sb + 15360, pB + _k0 + rstepB);                                 \
    } while (0)

    LOAD_S1(0); asm volatile("cp.async.commit_group;" ::: "memory");
    LOAD_S1(1); asm volatile("cp.async.commit_group;" ::: "memory");
    LOAD_S1(2); asm volatile("cp.async.commit_group;" ::: "memory");

    const uint32_t aoff = ((wm + (lane & 15)) * 40 + ((lane >> 4) << 3)) * 2;
    const uint32_t boff = ((wn + (lane & 7) + ((lane >> 4) << 3)) * 40 + (lane & 8)) * 2;

    for (int kt = 0; kt < KT; ++kt) {
        asm volatile("cp.async.wait_group 2;" ::: "memory");
        __syncthreads();
        const uint32_t sb = sbase + (kt & 3) * STAGEB1;

        #pragma unroll
        for (int ks = 0; ks < 2; ++ks) {
            const uint32_t kc2 = ks * 32;
            uint32_t af[4][4], bf[4][2];
            #pragma unroll
            for (int mt = 0; mt < 4; mt++)
                ldsm4(af[mt], sb + aoff + kc2 + mt * 1280);
            #pragma unroll
            for (int n2 = 0; n2 < 2; n2++) {
                uint32_t r[4];
                ldsm4(r, sb + 10240 + boff + kc2 + n2 * 1280);
                bf[n2 * 2][0] = r[0]; bf[n2 * 2][1] = r[1];
                bf[n2 * 2 + 1][0] = r[2]; bf[n2 * 2 + 1][1] = r[3];
            }
            #pragma unroll
            for (int mt = 0; mt < 4; mt++)
                #pragma unroll
                for (int nt = 0; nt < 4; nt++)
                    mma16816(acc[mt][nt], af[mt], bf[nt]);
        }
        __syncthreads();
        if (kt + 3 < KT) LOAD_S1(kt + 3);
        asm volatile("cp.async.commit_group;" ::: "memory");
    }

    #pragma unroll
    for (int mt = 0; mt < 4; mt++) {
        const int row = bm + wm + mt * 16 + (lane >> 2);
        float* r0 = C + (size_t)row * ldc + bn + wn + (lane & 3) * 2;
        float* r1 = r0 + (size_t)8 * ldc;
        #pragma unroll
        for (int nt = 0; nt < 4; nt++) {
            *(float2*)(r0 + nt * 8) = make_float2(acc[mt][nt][0], acc[mt][nt][1]);
            *(float2*)(r1 + nt * 8) = make_float2(acc[mt][nt][2], acc[mt][nt][3]);
        }
    }
#undef LOAD_S1
}

// ---------------------------------------------------------------------------
// Launch
// ---------------------------------------------------------------------------
extern "C" void kernel_launch(void* const* d_in, const int* in_sizes, int n_in,
                              void* d_out, int out_size)
{
    const float* x = (const float*)d_in[0];   // [16384, 1024]
    const float* w = (const float*)d_in[1];   // [4096, 1024]
    float* out = (float*)d_out;               // [16384, 1024]

    float *scores;
    __half *xhi, *whi, *wthi, *phi;
    uint8_t *x8h, *x8l, *w8h, *w8l;
    cudaGetSymbolAddress((void**)&scores, g_scores);
    cudaGetSymbolAddress((void**)&xhi, g_xhi);
    cudaGetSymbolAddress((void**)&whi, g_whi);
    cudaGetSymbolAddress((void**)&wthi, g_wthi);
    cudaGetSymbolAddress((void**)&phi, g_phi);
    cudaGetSymbolAddress((void**)&x8h, g_x8h);
    cudaGetSymbolAddress((void**)&x8l, g_x8l);
    cudaGetSymbolAddress((void**)&w8h, g_w8h);
    cudaGetSymbolAddress((void**)&w8l, g_w8l);

    cudaFuncSetAttribute(gemm_mixed, cudaFuncAttributeMaxDynamicSharedMemorySize,
                         GSMEMM);
    cudaFuncSetAttribute(gemm_h16, cudaFuncAttributeMaxDynamicSharedMemorySize,
                         GSMEM1);

    // Prep: fused rmsnorm + planes; W transpose (fp16)
    rms_split_kernel<<<MROWS, 256>>>(x, xhi, x8h, x8l);
    rms_split_kernel<<<DF,    256>>>(w, whi, w8h, w8l);
    {
        dim3 g(DM / 32, DF / 32), b(32, 32);
        wt_kernel<<<g, b>>>(w, wthi);
    }

    // GEMM1 (fp16 hi*hi + fp8 cross, f16 acc): scores
    {
        dim3 g(DF / 128, MROWS / 128);   // 32 x 128
        gemm_mixed<<<g, 256, GSMEMM>>>(xhi, whi, x8h, x8l, w8h, w8l, scores);
    }

    // softmax rows -> fp16 probs
    softmax_h<<<MROWS, 256>>>(scores, phi);

    // GEMM2 (1-term fp16)
    {
        dim3 g(DM / 128, MROWS / 128);   // 8 x 128
        gemm_h16<<<g, 256, GSMEM1>>>(phi, wthi, out, DF, DF, DM, DF / 32);
    }
}

// round 9
// speedup vs baseline: 1.2386x; 1.1792x over previous
#include <cuda_runtime.h>
#include <cuda_fp16.h>
#include <cstdint>
#include <math_constants.h>

// Problem dims (fixed per reference)
#define DM   1024      // d_model
#define DF   4096      // d_ff
#define MROWS 16384    // 4 * 4096

// ---------------------------------------------------------------------------
// Scratch (allocation-free: __device__ globals)
// ---------------------------------------------------------------------------
__device__ float  g_scores[(size_t)MROWS * DF];   // 256 MB fp32 logits
__device__ __half g_phi[(size_t)MROWS * DF];      // probs (single fp16)
__device__ __half g_xhi[(size_t)MROWS * DM];      // rmsnorm(x) hi
__device__ __half g_xlo[(size_t)MROWS * DM];      // rmsnorm(x) lo
__device__ __half g_whi[(size_t)DF * DM];         // rmsnorm(w) hi
__device__ __half g_wlo[(size_t)DF * DM];         // rmsnorm(w) lo
__device__ __half g_wthi[(size_t)DM * DF];        // W^T (raw w) [d][c]
// ---------------------------------------------------------------------------
// PTX helpers
// ---------------------------------------------------------------------------
__device__ __forceinline__ uint32_t smem_u32_of(const void* p) {
    uint32_t a;
    asm("{ .reg .u64 t; cvta.to.shared.u64 t, %1; cvt.u32.u64 %0, t; }" : "=r"(a) : "l"(p));
    return a;
}

__device__ __forceinline__ void cp16(uint32_t s, const void* g) {
    asm volatile("cp.async.cg.shared.global [%0], [%1], 16;" :: "r"(s), "l"(g));
}

__device__ __forceinline__ void ldsm4(uint32_t* r, uint32_t a) {
    asm volatile("ldmatrix.sync.aligned.m8n8.x4.shared.b16 {%0,%1,%2,%3}, [%4];"
                 : "=r"(r[0]), "=r"(r[1]), "=r"(r[2]), "=r"(r[3]) : "r"(a));
}

__device__ __forceinline__ void mma16816(float* d, const uint32_t* a, const uint32_t* b) {
    asm volatile(
        "mma.sync.aligned.m16n8k16.row.col.f32.f16.f16.f32 "
        "{%0,%1,%2,%3}, {%4,%5,%6,%7}, {%8,%9}, {%0,%1,%2,%3};"
        : "+f"(d[0]), "+f"(d[1]), "+f"(d[2]), "+f"(d[3])
        : "r"(a[0]), "r"(a[1]), "r"(a[2]), "r"(a[3]), "r"(b[0]), "r"(b[1]));
}

// f16-accumulator variant (2-reg D fragment; same thread/element mapping)
__device__ __forceinline__ void mma16816h(uint32_t* d, const uint32_t* a, const uint32_t* b) {
    asm volatile(
        "mma.sync.aligned.m16n8k16.row.col.f16.f16.f16.f16 "
        "{%0,%1}, {%2,%3,%4,%5}, {%6,%7}, {%0,%1};"
        : "+r"(d[0]), "+r"(d[1])
        : "r"(a[0]), "r"(a[1]), "r"(a[2]), "r"(a[3]), "r"(b[0]), "r"(b[1]));
}

// ---------------------------------------------------------------------------
// Kernel: fused per-row rmsnorm + fp16 hi/lo split.
// One block (256 thr) per row of 1024 floats.
// ---------------------------------------------------------------------------
__device__ __forceinline__ void split2h(float v, __half& h, __half& l) {
    h = __float2half_rn(v);
    l = __float2half_rn(v - __half2float(h));
}

__global__ __launch_bounds__(256) void rms_split_kernel(
    const float* __restrict__ src,
    __half* __restrict__ hi, __half* __restrict__ lo)
{
    const int row = blockIdx.x;
    const int tid = threadIdx.x;
    const size_t base = (size_t)row * DM;

    float4 v = *(const float4*)(src + base + tid * 4);
    float ss = v.x * v.x + v.y * v.y + v.z * v.z + v.w * v.w;

    __shared__ float red[256];
    red[tid] = ss;
    __syncthreads();
    #pragma unroll
    for (int off = 128; off > 0; off >>= 1) {
        if (tid < off) red[tid] += red[tid + off];
        __syncthreads();
    }
    const float s = rsqrtf(red[0] * (1.0f / DM) + 1e-6f);

    __half h0, h1, h2, h3, l0, l1, l2, l3;
    split2h(v.x * s, h0, l0); split2h(v.y * s, h1, l1);
    split2h(v.z * s, h2, l2); split2h(v.w * s, h3, l3);
    __half2* H = (__half2*)(hi + base + tid * 4);
    __half2* L = (__half2*)(lo + base + tid * 4);
    H[0] = __halves2half2(h0, h1); H[1] = __halves2half2(h2, h3);
    L[0] = __halves2half2(l0, l1); L[1] = __halves2half2(l2, l3);
}

// ---------------------------------------------------------------------------
// Kernel: transpose  W[c,d] -> Wt[d,c]  (raw w, single fp16)
// ---------------------------------------------------------------------------
__global__ void wt_kernel(const float* __restrict__ w, __half* __restrict__ th)
{
    __shared__ float t[32][33];
    const int c = blockIdx.y * 32 + threadIdx.y;
    const int d = blockIdx.x * 32 + threadIdx.x;
    t[threadIdx.y][threadIdx.x] = w[(size_t)c * DM + d];
    __syncthreads();
    const int dd = blockIdx.x * 32 + threadIdx.y;
    const int cc = blockIdx.y * 32 + threadIdx.x;
    th[(size_t)dd * DF + cc] = __float2half_rn(t[threadIdx.x][threadIdx.y]);
}

// ---------------------------------------------------------------------------
// Kernel: row softmax over 4096, emits single fp16 probs
// ---------------------------------------------------------------------------
__global__ __launch_bounds__(256) void softmax_h(const float* __restrict__ S,
                                                 __half* __restrict__ PH)
{
    const int row = blockIdx.x;
    const int tid = threadIdx.x;
    const float* p = S + (size_t)row * DF + tid * 16;

    float v[16];
    #pragma unroll
    for (int j = 0; j < 4; j++) {
        float4 t = *(const float4*)(p + j * 4);
        v[j * 4 + 0] = t.x; v[j * 4 + 1] = t.y;
        v[j * 4 + 2] = t.z; v[j * 4 + 3] = t.w;
    }
    float lm = v[0];
    #pragma unroll
    for (int j = 1; j < 16; j++) lm = fmaxf(lm, v[j]);

    __shared__ float red[256];
    red[tid] = lm;
    __syncthreads();
    #pragma unroll
    for (int off = 128; off > 0; off >>= 1) {
        if (tid < off) red[tid] = fmaxf(red[tid], red[tid + off]);
        __syncthreads();
    }
    const float m = red[0];
    __syncthreads();

    float ls = 0.f;
    #pragma unroll
    for (int j = 0; j < 16; j++) {
        v[j] = __expf(v[j] - m);
        ls += v[j];
    }
    red[tid] = ls;
    __syncthreads();
    #pragma unroll
    for (int off = 128; off > 0; off >>= 1) {
        if (tid < off) red[tid] += red[tid + off];
        __syncthreads();
    }
    const float inv = 1.0f / red[0];

    __half2* ph2 = (__half2*)(PH + (size_t)row * DF + tid * 16);
    #pragma unroll
    for (int j = 0; j < 8; j++) {
        ph2[j] = __halves2half2(__float2half_rn(v[2 * j] * inv),
                                __float2half_rn(v[2 * j + 1] * inv));
    }
}

// ---------------------------------------------------------------------------
// GEMM1: split-fp16 NT GEMM via mma.sync.m16n8k16.
//   main  : Ah*Bh  with f32 accumulation (exact hi term)
//   cross : Ah*Bl + Al*Bh with a SINGLE shared f16 accumulator set
// (cross sums ~5e-3 magnitude -> f16 acc error ~2e-5, negligible.)
// BM=BN=128, BK=32, 8 warps (2x4, 64x32 warp tile), 4-stage cp.async ring.
// Stage 40960 B: Ah@0 | Al@10240 | Bh@20480 | Bl@30720 (80B pitch rows).
// ---------------------------------------------------------------------------
#define STAGEB 40960
#define GSMEM  (4 * STAGEB)   // 163840

__global__ __launch_bounds__(256, 1) void gemm_hsplit(
    const __half* __restrict__ Ah, const __half* __restrict__ Al,
    const __half* __restrict__ Bh, const __half* __restrict__ Bl,
    float* __restrict__ C, int lda, int ldb, int ldc, int KT)
{
    extern __shared__ __align__(16) char smem[];
    const uint32_t sbase = smem_u32_of(smem);
    const int tid  = threadIdx.x;
    const int lane = tid & 31;
    const int wid  = tid >> 5;
    const int wm   = (wid >> 2) * 64;   // warp m offset (0,64)
    const int wn   = (wid & 3) * 32;    // warp n offset (0..96)
    const int bm   = blockIdx.y * 128;
    const int bn   = blockIdx.x * 128;

    const int lr = tid >> 2;
    const int lc = tid & 3;
    const __half* pAh = Ah + (size_t)(bm + lr) * lda + lc * 8;
    const __half* pAl = Al + (size_t)(bm + lr) * lda + lc * 8;
    const __half* pBh = Bh + (size_t)(bn + lr) * ldb + lc * 8;
    const __half* pBl = Bl + (size_t)(bn + lr) * ldb + lc * 8;
    const size_t rstepA = (size_t)64 * lda;
    const size_t rstepB = (size_t)64 * ldb;
    const uint32_t so = lr * 80 + lc * 16;

    float    accm[4][4][4];   // hi*hi, f32 acc
    uint32_t accx[4][4][2];   // cross terms, f16 acc (half2 pairs)
    #pragma unroll
    for (int i = 0; i < 4; i++)
        #pragma unroll
        for (int j = 0; j < 4; j++) {
            #pragma unroll
            for (int k = 0; k < 4; k++) accm[i][j][k] = 0.f;
            accx[i][j][0] = 0u; accx[i][j][1] = 0u;
        }

#define LOAD_STAGE(kt)                                                        \
    do {                                                                      \
        const int _k0 = (kt) * 32;                                            \
        const uint32_t _sb = sbase + ((kt) & 3) * STAGEB + so;                \
        cp16(_sb + 0,     pAh + _k0);                                         \
        cp16(_sb + 5120,  pAh + _k0 + rstepA);                                \
        cp16(_sb + 10240, pAl + _k0);                                         \
        cp16(_sb + 15360, pAl + _k0 + rstepA);                                \
        cp16(_sb + 20480, pBh + _k0);                                         \
        cp16(_sb + 25600, pBh + _k0 + rstepB);                                \
        cp16(_sb + 30720, pBl + _k0);                                         \
        cp16(_sb + 35840, pBl + _k0 + rstepB);                                \
    } while (0)

    LOAD_STAGE(0); asm volatile("cp.async.commit_group;" ::: "memory");
    LOAD_STAGE(1); asm volatile("cp.async.commit_group;" ::: "memory");
    LOAD_STAGE(2); asm volatile("cp.async.commit_group;" ::: "memory");

    const uint32_t aoff = ((wm + (lane & 15)) * 40 + ((lane >> 4) << 3)) * 2;
    const uint32_t boff = ((wn + (lane & 7) + ((lane >> 4) << 3)) * 40 + (lane & 8)) * 2;

    for (int kt = 0; kt < KT; ++kt) {
        asm volatile("cp.async.wait_group 2;" ::: "memory");
        __syncthreads();
        const uint32_t sb = sbase + (kt & 3) * STAGEB;

        #pragma unroll
        for (int ks = 0; ks < 2; ++ks) {
            const uint32_t kc2 = ks * 32;
            uint32_t ahf[4][4], alf[4][4], bhf[4][2], blf[4][2];
            #pragma unroll
            for (int mt = 0; mt < 4; mt++) {
                ldsm4(ahf[mt], sb + aoff + kc2 + mt * 1280);
                ldsm4(alf[mt], sb + 10240 + aoff + kc2 + mt * 1280);
            }
            #pragma unroll
            for (int n2 = 0; n2 < 2; n2++) {
                uint32_t r[4];
                ldsm4(r, sb + 20480 + boff + kc2 + n2 * 1280);
                bhf[n2 * 2][0] = r[0]; bhf[n2 * 2][1] = r[1];
                bhf[n2 * 2 + 1][0] = r[2]; bhf[n2 * 2 + 1][1] = r[3];
                ldsm4(r, sb + 30720 + boff + kc2 + n2 * 1280);
                blf[n2 * 2][0] = r[0]; blf[n2 * 2][1] = r[1];
                blf[n2 * 2 + 1][0] = r[2]; blf[n2 * 2 + 1][1] = r[3];
            }
            #pragma unroll
            for (int mt = 0; mt < 4; mt++)
                #pragma unroll
                for (int nt = 0; nt < 4; nt++) {
                    mma16816(accm[mt][nt], ahf[mt], bhf[nt]);    // hi*hi (f32)
                    mma16816h(accx[mt][nt], ahf[mt], blf[nt]);   // hi*lo (f16)
                    mma16816h(accx[mt][nt], alf[mt], bhf[nt]);   // lo*hi (f16)
                }
        }
        __syncthreads();
        if (kt + 3 < KT) LOAD_STAGE(kt + 3);
        asm volatile("cp.async.commit_group;" ::: "memory");
    }

    #pragma unroll
    for (int mt = 0; mt < 4; mt++) {
        const int row = bm + wm + mt * 16 + (lane >> 2);
        float* r0 = C + (size_t)row * ldc + bn + wn + (lane & 3) * 2;
        float* r1 = r0 + (size_t)8 * ldc;
        #pragma unroll
        for (int nt = 0; nt < 4; nt++) {
            const __half2 x01 = *reinterpret_cast<const __half2*>(&accx[mt][nt][0]);
            const __half2 x23 = *reinterpret_cast<const __half2*>(&accx[mt][nt][1]);
            *(float2*)(r0 + nt * 8) = make_float2(
                accm[mt][nt][0] + __low2float(x01),
                accm[mt][nt][1] + __high2float(x01));
            *(float2*)(r1 + nt * 8) = make_float2(
                accm[mt][nt][2] + __low2float(x23),
                accm[mt][nt][3] + __high2float(x23));
        }
    }
#undef LOAD_STAGE
}

// ---------------------------------------------------------------------------
// GEMM2: single-fp16 NT GEMM (1 term, f32 acc) — out = P @ W.
// BM=BN=128, BK=32, warp tile 64x32, 4-stage (R5-proven).
// ---------------------------------------------------------------------------
#define STAGEB1 20480
#define GSMEM1  (4 * STAGEB1)   // 81920

__global__ __launch_bounds__(256, 1) void gemm_h16(
    const __half* __restrict__ A, const __half* __restrict__ B,
    float* __restrict__ C, int lda, int ldb, int ldc, int KT)
{
    extern __shared__ __align__(16) char smem[];
    const uint32_t sbase = smem_u32_of(smem);
    const int tid  = threadIdx.x;
    const int lane = tid & 31;
    const int wid  = tid >> 5;
    const int wm   = (wid >> 2) * 64;
    const int wn   = (wid & 3) * 32;
    const int bm   = blockIdx.y * 128;
    const int bn   = blockIdx.x * 128;

    const int lr = tid >> 2;
    const int lc = tid & 3;
    const __half* pA = A + (size_t)(bm + lr) * lda + lc * 8;
    const __half* pB = B + (size_t)(bn + lr) * ldb + lc * 8;
    const size_t rstepA = (size_t)64 * lda;
    const size_t rstepB = (size_t)64 * ldb;
    const uint32_t so = lr * 80 + lc * 16;

    float acc[4][4][4];
    #pragma unroll
    for (int i = 0; i < 4; i++)
        #pragma unroll
        for (int j = 0; j < 4; j++)
            #pragma unroll
            for (int k = 0; k < 4; k++) acc[i][j][k] = 0.f;

#define LOAD_S1(kt)                                                           \
    do {                                                                      \
        const int _k0 = (kt) * 32;                                            \
        const uint32_t _sb = sbase + ((kt) & 3) * STAGEB1 + so;               \
        cp16(_sb + 0,     pA + _k0);                                          \
        cp16(_sb + 5120,  pA + _k0 + rstepA);                                 \
        cp16(_sb + 10240, pB + _k0);                                          \
        cp16(_sb + 15360, pB + _k0 + rstepB);                                 \
    } while (0)

    LOAD_S1(0); asm volatile("cp.async.commit_group;" ::: "memory");
    LOAD_S1(1); asm volatile("cp.async.commit_group;" ::: "memory");
    LOAD_S1(2); asm volatile("cp.async.commit_group;" ::: "memory");

    const uint32_t aoff = ((wm + (lane & 15)) * 40 + ((lane >> 4) << 3)) * 2;
    const uint32_t boff = ((wn + (lane & 7) + ((lane >> 4) << 3)) * 40 + (lane & 8)) * 2;

    for (int kt = 0; kt < KT; ++kt) {
        asm volatile("cp.async.wait_group 2;" ::: "memory");
        __syncthreads();
        const uint32_t sb = sbase + (kt & 3) * STAGEB1;

        #pragma unroll
        for (int ks = 0; ks < 2; ++ks) {
            const uint32_t kc2 = ks * 32;
            uint32_t af[4][4], bf[4][2];
            #pragma unroll
            for (int mt = 0; mt < 4; mt++)
                ldsm4(af[mt], sb + aoff + kc2 + mt * 1280);
            #pragma unroll
            for (int n2 = 0; n2 < 2; n2++) {
                uint32_t r[4];
                ldsm4(r, sb + 10240 + boff + kc2 + n2 * 1280);
                bf[n2 * 2][0] = r[0]; bf[n2 * 2][1] = r[1];
                bf[n2 * 2 + 1][0] = r[2]; bf[n2 * 2 + 1][1] = r[3];
            }
            #pragma unroll
            for (int mt = 0; mt < 4; mt++)
                #pragma unroll
                for (int nt = 0; nt < 4; nt++)
                    mma16816(acc[mt][nt], af[mt], bf[nt]);
        }
        __syncthreads();
        if (kt + 3 < KT) LOAD_S1(kt + 3);
        asm volatile("cp.async.commit_group;" ::: "memory");
    }

    #pragma unroll
    for (int mt = 0; mt < 4; mt++) {
        const int row = bm + wm + mt * 16 + (lane >> 2);
        float* r0 = C + (size_t)row * ldc + bn + wn + (lane & 3) * 2;
        float* r1 = r0 + (size_t)8 * ldc;
        #pragma unroll
        for (int nt = 0; nt < 4; nt++) {
            *(float2*)(r0 + nt * 8) = make_float2(acc[mt][nt][0], acc[mt][nt][1]);
            *(float2*)(r1 + nt * 8) = make_float2(acc[mt][nt][2], acc[mt][nt][3]);
        }
    }
#undef LOAD_S1
}

// ---------------------------------------------------------------------------
// Launch
// ---------------------------------------------------------------------------
extern "C" void kernel_launch(void* const* d_in, const int* in_sizes, int n_in,
                              void* d_out, int out_size)
{
    const float* x = (const float*)d_in[0];   // [16384, 1024]
    const float* w = (const float*)d_in[1];   // [4096, 1024]
    float* out = (float*)d_out;               // [16384, 1024]

    float *scores;
    __half *xhi, *xlo, *whi, *wlo, *wthi, *phi;
    cudaGetSymbolAddress((void**)&scores, g_scores);
    cudaGetSymbolAddress((void**)&xhi, g_xhi);
    cudaGetSymbolAddress((void**)&xlo, g_xlo);
    cudaGetSymbolAddress((void**)&whi, g_whi);
    cudaGetSymbolAddress((void**)&wlo, g_wlo);
    cudaGetSymbolAddress((void**)&wthi, g_wthi);
    cudaGetSymbolAddress((void**)&phi, g_phi);

    cudaFuncSetAttribute(gemm_hsplit, cudaFuncAttributeMaxDynamicSharedMemorySize,
                         GSMEM);
    cudaFuncSetAttribute(gemm_h16, cudaFuncAttributeMaxDynamicSharedMemorySize,
                         GSMEM1);

    // Prep: fused rmsnorm + fp16 hi/lo splits; W transpose (fp16)
    rms_split_kernel<<<MROWS, 256>>>(x, xhi, xlo);
    rms_split_kernel<<<DF,    256>>>(w, whi, wlo);
    {
        dim3 g(DM / 32, DF / 32), b(32, 32);
        wt_kernel<<<g, b>>>(w, wthi);
    }

    // GEMM1 (hi*hi f32 acc + cross f16 acc): scores
    {
        dim3 g(DF / 128, MROWS / 128);   // 32 x 128
        gemm_hsplit<<<g, 256, GSMEM>>>(xhi, xlo, whi, wlo, scores,
                                       DM, DM, DF, DM / 32);
    }

    // softmax rows -> fp16 probs
    softmax_h<<<MROWS, 256>>>(scores, phi);

    // GEMM2 (1-term fp16, f32 acc)
    {
        dim3 g(DM / 128, MROWS / 128);   // 8 x 128
        gemm_h16<<<g, 256, GSMEM1>>>(phi, wthi, out, DF, DF, DM, DF / 32);
    }
}

// round 10
// speedup vs baseline: 1.2438x; 1.0043x over previous
#include <cuda_runtime.h>
#include <cuda_fp16.h>
#include <cstdint>
#include <math_constants.h>

// Problem dims (fixed per reference)
#define DM   1024      // d_model
#define DF   4096      // d_ff
#define MROWS 16384    // 4 * 4096

// ---------------------------------------------------------------------------
// Scratch (allocation-free: __device__ globals)
// ---------------------------------------------------------------------------
__device__ float  g_scores[(size_t)MROWS * DF];   // 256 MB fp32 logits
__device__ __half g_phi[(size_t)MROWS * DF];      // probs (single fp16)
__device__ __half g_xhi[(size_t)MROWS * DM];      // rmsnorm(x) hi
__device__ __half g_xlo[(size_t)MROWS * DM];      // rmsnorm(x) lo
__device__ __half g_whi[(size_t)DF * DM];         // rmsnorm(w) hi
__device__ __half g_wlo[(size_t)DF * DM];         // rmsnorm(w) lo
__device__ __half g_wthi[(size_t)DM * DF];        // W^T (raw w) [d][c]

// ---------------------------------------------------------------------------
// PTX helpers
// ---------------------------------------------------------------------------
__device__ __forceinline__ uint32_t smem_u32_of(const void* p) {
    uint32_t a;
    asm("{ .reg .u64 t; cvta.to.shared.u64 t, %1; cvt.u32.u64 %0, t; }" : "=r"(a) : "l"(p));
    return a;
}

__device__ __forceinline__ void cp16(uint32_t s, const void* g) {
    asm volatile("cp.async.cg.shared.global [%0], [%1], 16;" :: "r"(s), "l"(g));
}

__device__ __forceinline__ void ldsm4(uint32_t* r, uint32_t a) {
    asm volatile("ldmatrix.sync.aligned.m8n8.x4.shared.b16 {%0,%1,%2,%3}, [%4];"
                 : "=r"(r[0]), "=r"(r[1]), "=r"(r[2]), "=r"(r[3]) : "r"(a));
}

__device__ __forceinline__ void mma16816(float* d, const uint32_t* a, const uint32_t* b) {
    asm volatile(
        "mma.sync.aligned.m16n8k16.row.col.f32.f16.f16.f32 "
        "{%0,%1,%2,%3}, {%4,%5,%6,%7}, {%8,%9}, {%0,%1,%2,%3};"
        : "+f"(d[0]), "+f"(d[1]), "+f"(d[2]), "+f"(d[3])
        : "r"(a[0]), "r"(a[1]), "r"(a[2]), "r"(a[3]), "r"(b[0]), "r"(b[1]));
}

// f16-accumulator variant (2-reg D fragment; same thread/element mapping)
__device__ __forceinline__ void mma16816h(uint32_t* d, const uint32_t* a, const uint32_t* b) {
    asm volatile(
        "mma.sync.aligned.m16n8k16.row.col.f16.f16.f16.f16 "
        "{%0,%1}, {%2,%3,%4,%5}, {%6,%7}, {%0,%1};"
        : "+r"(d[0]), "+r"(d[1])
        : "r"(a[0]), "r"(a[1]), "r"(a[2]), "r"(a[3]), "r"(b[0]), "r"(b[1]));
}

// ---------------------------------------------------------------------------
// Kernel: fused per-row rmsnorm + fp16 hi/lo split.
// ---------------------------------------------------------------------------
__device__ __forceinline__ void split2h(float v, __half& h, __half& l) {
    h = __float2half_rn(v);
    l = __float2half_rn(v - __half2float(h));
}

__global__ __launch_bounds__(256) void rms_split_kernel(
    const float* __restrict__ src,
    __half* __restrict__ hi, __half* __restrict__ lo)
{
    const int row = blockIdx.x;
    const int tid = threadIdx.x;
    const size_t base = (size_t)row * DM;

    float4 v = *(const float4*)(src + base + tid * 4);
    float ss = v.x * v.x + v.y * v.y + v.z * v.z + v.w * v.w;

    __shared__ float red[256];
    red[tid] = ss;
    __syncthreads();
    #pragma unroll
    for (int off = 128; off > 0; off >>= 1) {
        if (tid < off) red[tid] += red[tid + off];
        __syncthreads();
    }
    const float s = rsqrtf(red[0] * (1.0f / DM) + 1e-6f);

    __half h0, h1, h2, h3, l0, l1, l2, l3;
    split2h(v.x * s, h0, l0); split2h(v.y * s, h1, l1);
    split2h(v.z * s, h2, l2); split2h(v.w * s, h3, l3);
    __half2* H = (__half2*)(hi + base + tid * 4);
    __half2* L = (__half2*)(lo + base + tid * 4);
    H[0] = __halves2half2(h0, h1); H[1] = __halves2half2(h2, h3);
    L[0] = __halves2half2(l0, l1); L[1] = __halves2half2(l2, l3);
}

// ---------------------------------------------------------------------------
// Kernel: transpose  W[c,d] -> Wt[d,c]  (raw w, single fp16)
// ---------------------------------------------------------------------------
__global__ void wt_kernel(const float* __restrict__ w, __half* __restrict__ th)
{
    __shared__ float t[32][33];
    const int c = blockIdx.y * 32 + threadIdx.y;
    const int d = blockIdx.x * 32 + threadIdx.x;
    t[threadIdx.y][threadIdx.x] = w[(size_t)c * DM + d];
    __syncthreads();
    const int dd = blockIdx.x * 32 + threadIdx.y;
    const int cc = blockIdx.y * 32 + threadIdx.x;
    th[(size_t)dd * DF + cc] = __float2half_rn(t[threadIdx.x][threadIdx.y]);
}

// ---------------------------------------------------------------------------
// Kernel: row softmax over 4096, emits single fp16 probs
// ---------------------------------------------------------------------------
__global__ __launch_bounds__(256) void softmax_h(const float* __restrict__ S,
                                                 __half* __restrict__ PH)
{
    const int row = blockIdx.x;
    const int tid = threadIdx.x;
    const float* p = S + (size_t)row * DF + tid * 16;

    float v[16];
    #pragma unroll
    for (int j = 0; j < 4; j++) {
        float4 t = *(const float4*)(p + j * 4);
        v[j * 4 + 0] = t.x; v[j * 4 + 1] = t.y;
        v[j * 4 + 2] = t.z; v[j * 4 + 3] = t.w;
    }
    float lm = v[0];
    #pragma unroll
    for (int j = 1; j < 16; j++) lm = fmaxf(lm, v[j]);

    __shared__ float red[256];
    red[tid] = lm;
    __syncthreads();
    #pragma unroll
    for (int off = 128; off > 0; off >>= 1) {
        if (tid < off) red[tid] = fmaxf(red[tid], red[tid + off]);
        __syncthreads();
    }
    const float m = red[0];
    __syncthreads();

    float ls = 0.f;
    #pragma unroll
    for (int j = 0; j < 16; j++) {
        v[j] = __expf(v[j] - m);
        ls += v[j];
    }
    red[tid] = ls;
    __syncthreads();
    #pragma unroll
    for (int off = 128; off > 0; off >>= 1) {
        if (tid < off) red[tid] += red[tid + off];
        __syncthreads();
    }
    const float inv = 1.0f / red[0];

    __half2* ph2 = (__half2*)(PH + (size_t)row * DF + tid * 16);
    #pragma unroll
    for (int j = 0; j < 8; j++) {
        ph2[j] = __halves2half2(__float2half_rn(v[2 * j] * inv),
                                __float2half_rn(v[2 * j + 1] * inv));
    }
}

// ---------------------------------------------------------------------------
// GEMM1: split-fp16 NT GEMM, 512 threads / 16 warps, warp tile 32x32.
//   main  : Ah*Bh  f32 acc;  cross: Ah*Bl + Al*Bh shared f16 acc.
// CTA 128x128, BK=32, 4-stage cp.async ring.
// Stage 40960 B: Ah@0 | Al@10240 | Bh@20480 | Bl@30720 (80B pitch rows).
// 16 warps = 4 per SMSP -> LDSM/barrier latency hidden behind other warps' MMAs.
// ---------------------------------------------------------------------------
#define STAGEB 40960
#define GSMEM  (4 * STAGEB)   // 163840

__global__ __launch_bounds__(512, 1) void gemm_hsplit(
    const __half* __restrict__ Ah, const __half* __restrict__ Al,
    const __half* __restrict__ Bh, const __half* __restrict__ Bl,
    float* __restrict__ C, int lda, int ldb, int ldc, int KT)
{
    extern __shared__ __align__(16) char smem[];
    const uint32_t sbase = smem_u32_of(smem);
    const int tid  = threadIdx.x;
    const int lane = tid & 31;
    const int wid  = tid >> 5;           // 0..15
    const int wm   = (wid >> 2) * 32;    // 0,32,64,96
    const int wn   = (wid & 3) * 32;     // 0,32,64,96
    const int bm   = blockIdx.y * 128;
    const int bn   = blockIdx.x * 128;

    // loader: 512 threads cover 128 rows x 4 chunks exactly once per plane
    const int lr = tid >> 2;             // 0..127
    const int lc = tid & 3;              // 16B chunk
    const __half* pAh = Ah + (size_t)(bm + lr) * lda + lc * 8;
    const __half* pAl = Al + (size_t)(bm + lr) * lda + lc * 8;
    const __half* pBh = Bh + (size_t)(bn + lr) * ldb + lc * 8;
    const __half* pBl = Bl + (size_t)(bn + lr) * ldb + lc * 8;
    const uint32_t so = lr * 80 + lc * 16;

    float    accm[2][4][4];   // hi*hi, f32 acc
    uint32_t accx[2][4][2];   // cross, f16 acc
    #pragma unroll
    for (int i = 0; i < 2; i++)
        #pragma unroll
        for (int j = 0; j < 4; j++) {
            #pragma unroll
            for (int k = 0; k < 4; k++) accm[i][j][k] = 0.f;
            accx[i][j][0] = 0u; accx[i][j][1] = 0u;
        }

#define LOAD_STAGE(kt)                                                        \
    do {                                                                      \
        const int _k0 = (kt) * 32;                                            \
        const uint32_t _sb = sbase + ((kt) & 3) * STAGEB + so;                \
        cp16(_sb + 0,     pAh + _k0);                                         \
        cp16(_sb + 10240, pAl + _k0);                                         \
        cp16(_sb + 20480, pBh + _k0);                                         \
        cp16(_sb + 30720, pBl + _k0);                                         \
    } while (0)

    LOAD_STAGE(0); asm volatile("cp.async.commit_group;" ::: "memory");
    LOAD_STAGE(1); asm volatile("cp.async.commit_group;" ::: "memory");
    LOAD_STAGE(2); asm volatile("cp.async.commit_group;" ::: "memory");

    const uint32_t aoff = ((wm + (lane & 15)) * 40 + ((lane >> 4) << 3)) * 2;
    const uint32_t boff = ((wn + (lane & 7) + ((lane >> 4) << 3)) * 40 + (lane & 8)) * 2;

    for (int kt = 0; kt < KT; ++kt) {
        asm volatile("cp.async.wait_group 2;" ::: "memory");
        __syncthreads();
        const uint32_t sb = sbase + (kt & 3) * STAGEB;

        #pragma unroll
        for (int ks = 0; ks < 2; ++ks) {
            const uint32_t kc2 = ks * 32;
            uint32_t ahf[2][4], alf[2][4], bhf[4][2], blf[4][2];
            #pragma unroll
            for (int mt = 0; mt < 2; mt++) {
                ldsm4(ahf[mt], sb + aoff + kc2 + mt * 1280);
                ldsm4(alf[mt], sb + 10240 + aoff + kc2 + mt * 1280);
            }
            #pragma unroll
            for (int n2 = 0; n2 < 2; n2++) {
                uint32_t r[4];
                ldsm4(r, sb + 20480 + boff + kc2 + n2 * 1280);
                bhf[n2 * 2][0] = r[0]; bhf[n2 * 2][1] = r[1];
                bhf[n2 * 2 + 1][0] = r[2]; bhf[n2 * 2 + 1][1] = r[3];
                ldsm4(r, sb + 30720 + boff + kc2 + n2 * 1280);
                blf[n2 * 2][0] = r[0]; blf[n2 * 2][1] = r[1];
                blf[n2 * 2 + 1][0] = r[2]; blf[n2 * 2 + 1][1] = r[3];
            }
            #pragma unroll
            for (int mt = 0; mt < 2; mt++)
                #pragma unroll
                for (int nt = 0; nt < 4; nt++) {
                    mma16816(accm[mt][nt], ahf[mt], bhf[nt]);    // hi*hi (f32)
                    mma16816h(accx[mt][nt], ahf[mt], blf[nt]);   // hi*lo (f16)
                    mma16816h(accx[mt][nt], alf[mt], bhf[nt]);   // lo*hi (f16)
                }
        }
        __syncthreads();
        if (kt + 3 < KT) LOAD_STAGE(kt + 3);
        asm volatile("cp.async.commit_group;" ::: "memory");
    }

    #pragma unroll
    for (int mt = 0; mt < 2; mt++) {
        const int row = bm + wm + mt * 16 + (lane >> 2);
        float* r0 = C + (size_t)row * ldc + bn + wn + (lane & 3) * 2;
        float* r1 = r0 + (size_t)8 * ldc;
        #pragma unroll
        for (int nt = 0; nt < 4; nt++) {
            const __half2 x01 = *reinterpret_cast<const __half2*>(&accx[mt][nt][0]);
            const __half2 x23 = *reinterpret_cast<const __half2*>(&accx[mt][nt][1]);
            *(float2*)(r0 + nt * 8) = make_float2(
                accm[mt][nt][0] + __low2float(x01),
                accm[mt][nt][1] + __high2float(x01));
            *(float2*)(r1 + nt * 8) = make_float2(
                accm[mt][nt][2] + __low2float(x23),
                accm[mt][nt][3] + __high2float(x23));
        }
    }
#undef LOAD_STAGE
}

// ---------------------------------------------------------------------------
// GEMM2: single-fp16 NT GEMM (1 term, f32 acc), 512 threads, warp tile 32x32.
// CTA 128x128, BK=32, 4-stage. Stage 20480 B: A@0 | B@10240.
// ---------------------------------------------------------------------------
#define STAGEB1 20480
#define GSMEM1  (4 * STAGEB1)   // 81920

__global__ __launch_bounds__(512, 1) void gemm_h16(
    const __half* __restrict__ A, const __half* __restrict__ B,
    float* __restrict__ C, int lda, int ldb, int ldc, int KT)
{
    extern __shared__ __align__(16) char smem[];
    const uint32_t sbase = smem_u32_of(smem);
    const int tid  = threadIdx.x;
    const int lane = tid & 31;
    const int wid  = tid >> 5;
    const int wm   = (wid >> 2) * 32;
    const int wn   = (wid & 3) * 32;
    const int bm   = blockIdx.y * 128;
    const int bn   = blockIdx.x * 128;

    const int lr = tid >> 2;
    const int lc = tid & 3;
    const __half* pA = A + (size_t)(bm + lr) * lda + lc * 8;
    const __half* pB = B + (size_t)(bn + lr) * ldb + lc * 8;
    const uint32_t so = lr * 80 + lc * 16;

    float acc[2][4][4];
    #pragma unroll
    for (int i = 0; i < 2; i++)
        #pragma unroll
        for (int j = 0; j < 4; j++)
            #pragma unroll
            for (int k = 0; k < 4; k++) acc[i][j][k] = 0.f;

#define LOAD_S1(kt)                                                           \
    do {                                                                      \
        const int _k0 = (kt) * 32;                                            \
        const uint32_t _sb = sbase + ((kt) & 3) * STAGEB1 + so;               \
        cp16(_sb + 0,     pA + _k0);                                          \
        cp16(_sb + 10240, pB + _k0);                                          \
    } while (0)

    LOAD_S1(0); asm volatile("cp.async.commit_group;" ::: "memory");
    LOAD_S1(1); asm volatile("cp.async.commit_group;" ::: "memory");
    LOAD_S1(2); asm volatile("cp.async.commit_group;" ::: "memory");

    const uint32_t aoff = ((wm + (lane & 15)) * 40 + ((lane >> 4) << 3)) * 2;
    const uint32_t boff = ((wn + (lane & 7) + ((lane >> 4) << 3)) * 40 + (lane & 8)) * 2;

    for (int kt = 0; kt < KT; ++kt) {
        asm volatile("cp.async.wait_group 2;" ::: "memory");
        __syncthreads();
        const uint32_t sb = sbase + (kt & 3) * STAGEB1;

        #pragma unroll
        for (int ks = 0; ks < 2; ++ks) {
            const uint32_t kc2 = ks * 32;
            uint32_t af[2][4], bf[4][2];
            #pragma unroll
            for (int mt = 0; mt < 2; mt++)
                ldsm4(af[mt], sb + aoff + kc2 + mt * 1280);
            #pragma unroll
            for (int n2 = 0; n2 < 2; n2++) {
                uint32_t r[4];
                ldsm4(r, sb + 10240 + boff + kc2 + n2 * 1280);
                bf[n2 * 2][0] = r[0]; bf[n2 * 2][1] = r[1];
                bf[n2 * 2 + 1][0] = r[2]; bf[n2 * 2 + 1][1] = r[3];
            }
            #pragma unroll
            for (int mt = 0; mt < 2; mt++)
                #pragma unroll
                for (int nt = 0; nt < 4; nt++)
                    mma16816(acc[mt][nt], af[mt], bf[nt]);
        }
        __syncthreads();
        if (kt + 3 < KT) LOAD_S1(kt + 3);
        asm volatile("cp.async.commit_group;" ::: "memory");
    }

    #pragma unroll
    for (int mt = 0; mt < 2; mt++) {
        const int row = bm + wm + mt * 16 + (lane >> 2);
        float* r0 = C + (size_t)row * ldc + bn + wn + (lane & 3) * 2;
        float* r1 = r0 + (size_t)8 * ldc;
        #pragma unroll
        for (int nt = 0; nt < 4; nt++) {
            *(float2*)(r0 + nt * 8) = make_float2(acc[mt][nt][0], acc[mt][nt][1]);
            *(float2*)(r1 + nt * 8) = make_float2(acc[mt][nt][2], acc[mt][nt][3]);
        }
    }
#undef LOAD_S1
}

// ---------------------------------------------------------------------------
// Launch
// ---------------------------------------------------------------------------
extern "C" void kernel_launch(void* const* d_in, const int* in_sizes, int n_in,
                              void* d_out, int out_size)
{
    const float* x = (const float*)d_in[0];   // [16384, 1024]
    const float* w = (const float*)d_in[1];   // [4096, 1024]
    float* out = (float*)d_out;               // [16384, 1024]

    float *scores;
    __half *xhi, *xlo, *whi, *wlo, *wthi, *phi;
    cudaGetSymbolAddress((void**)&scores, g_scores);
    cudaGetSymbolAddress((void**)&xhi, g_xhi);
    cudaGetSymbolAddress((void**)&xlo, g_xlo);
    cudaGetSymbolAddress((void**)&whi, g_whi);
    cudaGetSymbolAddress((void**)&wlo, g_wlo);
    cudaGetSymbolAddress((void**)&wthi, g_wthi);
    cudaGetSymbolAddress((void**)&phi, g_phi);

    cudaFuncSetAttribute(gemm_hsplit, cudaFuncAttributeMaxDynamicSharedMemorySize,
                         GSMEM);
    cudaFuncSetAttribute(gemm_h16, cudaFuncAttributeMaxDynamicSharedMemorySize,
                         GSMEM1);

    // Prep: fused rmsnorm + fp16 hi/lo splits; W transpose (fp16)
    rms_split_kernel<<<MROWS, 256>>>(x, xhi, xlo);
    rms_split_kernel<<<DF,    256>>>(w, whi, wlo);
    {
        dim3 g(DM / 32, DF / 32), b(32, 32);
        wt_kernel<<<g, b>>>(w, wthi);
    }

    // GEMM1 (hi*hi f32 acc + cross f16 acc): scores
    {
        dim3 g(DF / 128, MROWS / 128);   // 32 x 128
        gemm_hsplit<<<g, 512, GSMEM>>>(xhi, xlo, whi, wlo, scores,
                                       DM, DM, DF, DM / 32);
    }

    // softmax rows -> fp16 probs
    softmax_h<<<MROWS, 256>>>(scores, phi);

    // GEMM2 (1-term fp16, f32 acc)
    {
        dim3 g(DM / 128, MROWS / 128);   // 8 x 128
        gemm_h16<<<g, 512, GSMEM1>>>(phi, wthi, out, DF, DF, DM, DF / 32);
    }
}